// round 1
// baseline (speedup 1.0000x reference)
#include <cuda_runtime.h>

// out[b,n] = sum_{c,hw} x[b,c,hw] * W_s[n,hw] * W_d[n,c] + W_b[n]
// Stage as GEMM Y[(b,c), n] = X[(b*c), hw] @ W_s^T with fused weighted-channel
// reduction epilogue (multiply by W_d[n,c], reduce over the 128 c-rows of the
// CTA tile, atomicAdd into out which is pre-initialized with the bias).
//
// B=32, C=256, H=W=56 -> K=3136, N=1024, M=B*C=8192.

#define M_DIM 8192
#define N_DIM 1024
#define K_DIM 3136
#define C_DIM 256

// ---------- f32x2 packed helpers (Blackwell sm_100+) ----------
__device__ __forceinline__ unsigned long long pack2(float lo, float hi) {
    unsigned long long r;
    asm("mov.b64 %0, {%1, %2};" : "=l"(r) : "f"(lo), "f"(hi));
    return r;
}
__device__ __forceinline__ void fma2(unsigned long long& d,
                                     unsigned long long a,
                                     unsigned long long b) {
    asm("fma.rn.f32x2 %0, %1, %2, %3;" : "=l"(d) : "l"(a), "l"(b), "l"(d));
}
__device__ __forceinline__ float2 unpack2(unsigned long long v) {
    float2 f;
    asm("mov.b64 {%0, %1}, %2;" : "=f"(f.x), "=f"(f.y) : "l"(v));
    return f;
}

// ---------- init: out[b,n] = W_b[n] ----------
__global__ void init_out_kernel(const float* __restrict__ Wb,
                                float* __restrict__ out) {
    int i = blockIdx.x * blockDim.x + threadIdx.x;  // 0 .. 32767
    out[i] = Wb[i & (N_DIM - 1)];
}

// ---------- fused GEMM + weighted reduce ----------
// Tile: BM=128, BN=128, BK=16. 256 threads, each computes 8x8.
__global__ __launch_bounds__(256, 2)
void fused_gemm_kernel(const float* __restrict__ X,
                       const float* __restrict__ Ws,
                       const float* __restrict__ Wd,
                       float* __restrict__ out) {
    __shared__ float As[16][132];  // [k][m] transposed, padded
    __shared__ float Bs[16][132];  // [k][n] transposed, padded

    const int tid = threadIdx.x;
    const int tx = tid & 15;   // column group (n)
    const int ty = tid >> 4;   // row group (m = c)
    const int m0 = blockIdx.y * 128;
    const int n0 = blockIdx.x * 128;

    unsigned long long acc[8][4];
#pragma unroll
    for (int i = 0; i < 8; ++i)
#pragma unroll
        for (int j = 0; j < 4; ++j) acc[i][j] = 0ull;  // two packed +0.0f

    // Global load mapping: 256 threads cover 128 rows x 16 k in 2 iterations
    // of float4 loads along k.
    const int lrow = tid >> 2;          // 0..63
    const int lkq  = (tid & 3) * 4;     // 0,4,8,12
    const float* Aptr = X  + (long)(m0 + lrow) * K_DIM + lkq;
    const float* Bptr = Ws + (long)(n0 + lrow) * K_DIM + lkq;

    for (int k0 = 0; k0 < K_DIM; k0 += 16) {
#pragma unroll
        for (int it = 0; it < 2; ++it) {
            const int r = lrow + it * 64;
            float4 av = *(const float4*)(Aptr + (long)it * 64 * K_DIM + k0);
            float4 bv = *(const float4*)(Bptr + (long)it * 64 * K_DIM + k0);
            As[lkq + 0][r] = av.x; As[lkq + 1][r] = av.y;
            As[lkq + 2][r] = av.z; As[lkq + 3][r] = av.w;
            Bs[lkq + 0][r] = bv.x; Bs[lkq + 1][r] = bv.y;
            Bs[lkq + 2][r] = bv.z; Bs[lkq + 3][r] = bv.w;
        }
        __syncthreads();

#pragma unroll
        for (int k = 0; k < 16; ++k) {
            float4 a0 = *(const float4*)&As[k][ty * 8];
            float4 a1 = *(const float4*)&As[k][ty * 8 + 4];
            // B values for adjacent n are contiguous -> load pre-packed pairs.
            const unsigned long long* bp =
                (const unsigned long long*)&Bs[k][tx * 8];
            unsigned long long bb0 = bp[0], bb1 = bp[1],
                               bb2 = bp[2], bb3 = bp[3];
            float a[8] = {a0.x, a0.y, a0.z, a0.w, a1.x, a1.y, a1.z, a1.w};
#pragma unroll
            for (int i = 0; i < 8; ++i) {
                unsigned long long aa = pack2(a[i], a[i]);
                fma2(acc[i][0], aa, bb0);
                fma2(acc[i][1], aa, bb1);
                fma2(acc[i][2], aa, bb2);
                fma2(acc[i][3], aa, bb3);
            }
        }
        __syncthreads();
    }

    // ---------- epilogue: p[n] = sum_i acc[i][n] * W_d[n, c_i] ----------
    const int b = m0 >> 8;                       // BM=128 divides C=256
    const int cbase = (m0 & (C_DIM - 1)) + ty * 8;

    float accf[8][8];
#pragma unroll
    for (int i = 0; i < 8; ++i)
#pragma unroll
        for (int jp = 0; jp < 4; ++jp) {
            float2 v = unpack2(acc[i][jp]);
            accf[i][2 * jp]     = v.x;
            accf[i][2 * jp + 1] = v.y;
        }

    float p[8];
#pragma unroll
    for (int j = 0; j < 8; ++j) {
        const int n = n0 + tx * 8 + j;
        const float4* wp = (const float4*)(Wd + (long)n * C_DIM + cbase);
        float4 w0 = wp[0], w1 = wp[1];
        float w[8] = {w0.x, w0.y, w0.z, w0.w, w1.x, w1.y, w1.z, w1.w};
        float s = 0.f;
#pragma unroll
        for (int i = 0; i < 8; ++i) s += accf[i][j] * w[i];
        p[j] = s;
    }

    // Cross-thread reduction over ty (16 row-groups) per n column. Reuse As.
    __syncthreads();
#pragma unroll
    for (int j = 0; j < 8; ++j) As[ty][tx * 8 + j] = p[j];
    __syncthreads();

    if (tid < 128) {
        float s = 0.f;
#pragma unroll
        for (int t = 0; t < 16; ++t) s += As[t][tid];
        atomicAdd(out + b * N_DIM + n0 + tid, s);
    }
}

extern "C" void kernel_launch(void* const* d_in, const int* in_sizes, int n_in,
                              void* d_out, int out_size) {
    const float* x  = (const float*)d_in[0];  // (32,256,56,56)
    const float* Ws = (const float*)d_in[1];  // (1024,56,56)
    const float* Wd = (const float*)d_in[2];  // (1024,256,1,1)
    const float* Wb = (const float*)d_in[3];  // (1,1024)
    float* out = (float*)d_out;               // (32,1024)

    init_out_kernel<<<(32 * N_DIM) / 256, 256>>>(Wb, out);

    dim3 grid(N_DIM / 128, M_DIM / 128);  // (8, 64)
    fused_gemm_kernel<<<grid, 256>>>(x, Ws, Wd, out);
}

// round 3
// speedup vs baseline: 2.2167x; 2.2167x over previous
#include <cuda_runtime.h>
#include <cuda_bf16.h>
#include <cstdint>

// out[b,n] = sum_{c,hw} x[b,c,hw]*W_s[n,hw]*W_d[n,c] + W_b[n]
// GEMM Y[(b,c),n] = X[8192,3136] @ Ws[1024,3136]^T using mma.sync bf16
// (base sm_103 feature; tcgen05 needs sm_103a which this build lacks).
// Accuracy: bf16 2-term split, 3 MMAs: hi*hi + hi*lo + lo*hi.

#define K_DIM 3136
#define C_DIM 256
#define N_DIM 1024
#define M_DIM 8192
#define BM 128
#define BN 128
#define BK 32
#define NCHUNKS 98            // 3136/32
#define NSTAGE 3
#define TERM_B 10240          // 128 rows * 80B stride
#define STAGE_B 40960         // Ahi,Alo,Bhi,Blo
#define SMEM_TOTAL (NSTAGE * STAGE_B)

// ---------------- scratch (alloc-free) ----------------
__device__ __align__(256) __nv_bfloat16 g_Xhi[(long)M_DIM * K_DIM];
__device__ __align__(256) __nv_bfloat16 g_Xlo[(long)M_DIM * K_DIM];
__device__ __align__(256) __nv_bfloat16 g_Whi[(long)N_DIM * K_DIM];
__device__ __align__(256) __nv_bfloat16 g_Wlo[(long)N_DIM * K_DIM];

__device__ __forceinline__ uint32_t smem_u32(const void* p) {
    uint32_t a;
    asm("{ .reg .u64 t; cvta.to.shared.u64 t, %1; cvt.u32.u64 %0, t; }"
        : "=r"(a) : "l"(p));
    return a;
}
__device__ __forceinline__ void cp_async16(uint32_t dst, const void* src) {
    asm volatile("cp.async.cg.shared.global [%0], [%1], 16;"
                 :: "r"(dst), "l"(src));
}
__device__ __forceinline__ void cp_commit() {
    asm volatile("cp.async.commit_group;" ::: "memory");
}
template <int N>
__device__ __forceinline__ void cp_wait() {
    asm volatile("cp.async.wait_group %0;" :: "n"(N) : "memory");
}
__device__ __forceinline__ void ldsm4(uint32_t& r0, uint32_t& r1, uint32_t& r2,
                                      uint32_t& r3, uint32_t a) {
    asm volatile("ldmatrix.sync.aligned.m8n8.x4.shared.b16 {%0,%1,%2,%3}, [%4];"
                 : "=r"(r0), "=r"(r1), "=r"(r2), "=r"(r3) : "r"(a));
}
__device__ __forceinline__ void mma16816(float* c, const uint32_t* a,
                                         const uint32_t* b) {
    asm volatile(
        "mma.sync.aligned.m16n8k16.row.col.f32.bf16.bf16.f32 "
        "{%0,%1,%2,%3}, {%4,%5,%6,%7}, {%8,%9}, {%0,%1,%2,%3};"
        : "+f"(c[0]), "+f"(c[1]), "+f"(c[2]), "+f"(c[3])
        : "r"(a[0]), "r"(a[1]), "r"(a[2]), "r"(a[3]), "r"(b[0]), "r"(b[1]));
}

// ---------------- split conversion ----------------
__global__ void split_x_kernel(const float* __restrict__ src) {
    long i = ((long)blockIdx.x * blockDim.x + threadIdx.x) * 4;
    if (i >= (long)M_DIM * K_DIM) return;
    float4 v = *(const float4*)(src + i);
    float f[4] = {v.x, v.y, v.z, v.w};
    __nv_bfloat16 h[4], l[4];
#pragma unroll
    for (int j = 0; j < 4; ++j) {
        h[j] = __float2bfloat16(f[j]);
        l[j] = __float2bfloat16(f[j] - __bfloat162float(h[j]));
    }
    __nv_bfloat162* H = (__nv_bfloat162*)(g_Xhi + i);
    __nv_bfloat162* L = (__nv_bfloat162*)(g_Xlo + i);
    H[0] = __halves2bfloat162(h[0], h[1]);
    H[1] = __halves2bfloat162(h[2], h[3]);
    L[0] = __halves2bfloat162(l[0], l[1]);
    L[1] = __halves2bfloat162(l[2], l[3]);
}
__global__ void split_w_kernel(const float* __restrict__ src) {
    long i = ((long)blockIdx.x * blockDim.x + threadIdx.x) * 4;
    if (i >= (long)N_DIM * K_DIM) return;
    float4 v = *(const float4*)(src + i);
    float f[4] = {v.x, v.y, v.z, v.w};
    __nv_bfloat16 h[4], l[4];
#pragma unroll
    for (int j = 0; j < 4; ++j) {
        h[j] = __float2bfloat16(f[j]);
        l[j] = __float2bfloat16(f[j] - __bfloat162float(h[j]));
    }
    __nv_bfloat162* H = (__nv_bfloat162*)(g_Whi + i);
    __nv_bfloat162* L = (__nv_bfloat162*)(g_Wlo + i);
    H[0] = __halves2bfloat162(h[0], h[1]);
    H[1] = __halves2bfloat162(h[2], h[3]);
    L[0] = __halves2bfloat162(l[0], l[1]);
    L[1] = __halves2bfloat162(l[2], l[3]);
}

__global__ void init_out_kernel(const float* __restrict__ Wb,
                                float* __restrict__ out) {
    int i = blockIdx.x * blockDim.x + threadIdx.x;
    out[i] = Wb[i & (N_DIM - 1)];
}

// ---------------- main GEMM ----------------
// smem per stage: Ahi[128][80B] Alo Bhi Blo. 80B stride -> conflict-free
// ldmatrix (row-group pattern (5*r)%8 covers all 8 16B groups).
__global__ __launch_bounds__(256)
void gemm_kernel(const float* __restrict__ Wd, float* __restrict__ out) {
    extern __shared__ char smem[];
    const uint32_t sb = smem_u32(smem);
    const int tid = threadIdx.x;
    const int lane = tid & 31;
    const int warp = tid >> 5;
    const int m0 = blockIdx.y * BM;
    const int n0 = blockIdx.x * BN;
    const int mwarp = (warp >> 2) * 64;   // 2 warp-rows
    const int nwarp = (warp & 3) * 32;    // 4 warp-cols

    float acc[4][4][4];
#pragma unroll
    for (int i = 0; i < 4; ++i)
#pragma unroll
        for (int j = 0; j < 4; ++j)
#pragma unroll
            for (int k = 0; k < 4; ++k) acc[i][j][k] = 0.f;

    // ldmatrix per-lane offsets
    const uint32_t a_lo = (uint32_t)((lane & 15) * 80 + ((lane >> 4) & 1) * 16);
    const uint32_t b_lo =
        (uint32_t)(((lane & 7) + ((lane >> 4) & 1) * 8) * 80 +
                   ((lane >> 3) & 1) * 16);

    // cp.async mapping: per tensor-part 512 16B chunks, 2 per thread
    const int lrow = tid >> 2;        // 0..63 (+64 on second step)
    const int lch = (tid & 3) * 16;   // byte offset in row

    auto load_chunk = [&](int chunk, int s) {
        const long k0 = (long)chunk * BK;
        const uint32_t st = sb + (uint32_t)s * STAGE_B;
#pragma unroll
        for (int u = 0; u < 2; ++u) {
            const int row = lrow + u * 64;
            const long gx = (long)(m0 + row) * K_DIM + k0;
            const long gw = (long)(n0 + row) * K_DIM + k0;
            const uint32_t sa = st + (uint32_t)(row * 80) + lch;
            cp_async16(sa,             (const char*)(g_Xhi + gx) + lch * 1);
            cp_async16(sa + TERM_B,    (const char*)(g_Xlo + gx) + lch * 1);
            cp_async16(sa + 2 * TERM_B, (const char*)(g_Whi + gw) + lch * 1);
            cp_async16(sa + 3 * TERM_B, (const char*)(g_Wlo + gw) + lch * 1);
        }
    };

    load_chunk(0, 0); cp_commit();
    load_chunk(1, 1); cp_commit();

    for (int i = 0; i < NCHUNKS; ++i) {
        __syncthreads();   // everyone done computing chunk i-1 (stage reuse)
        if (i + 2 < NCHUNKS) { load_chunk(i + 2, (i + 2) % NSTAGE); cp_commit(); }
        if (i + 2 < NCHUNKS) cp_wait<2>();
        else if (i + 1 < NCHUNKS) cp_wait<1>();
        else cp_wait<0>();
        __syncthreads();

        const uint32_t st = sb + (uint32_t)(i % NSTAGE) * STAGE_B;
        const uint32_t Ah = st + (uint32_t)(mwarp * 80) + a_lo;
        const uint32_t Bh = st + 2 * TERM_B + (uint32_t)(nwarp * 80) + b_lo;
#pragma unroll
        for (int ks = 0; ks < 2; ++ks) {
            uint32_t ahi[4][4], alo[4][4], bhi[4][2], blo[4][2];
#pragma unroll
            for (int mi = 0; mi < 4; ++mi) {
                const uint32_t aa = Ah + (uint32_t)(mi * 16 * 80 + ks * 32);
                ldsm4(ahi[mi][0], ahi[mi][1], ahi[mi][2], ahi[mi][3], aa);
                ldsm4(alo[mi][0], alo[mi][1], alo[mi][2], alo[mi][3],
                      aa + TERM_B);
            }
#pragma unroll
            for (int seg = 0; seg < 2; ++seg) {
                const uint32_t ba = Bh + (uint32_t)(seg * 16 * 80 + ks * 32);
                ldsm4(bhi[2 * seg][0], bhi[2 * seg][1], bhi[2 * seg + 1][0],
                      bhi[2 * seg + 1][1], ba);
                ldsm4(blo[2 * seg][0], blo[2 * seg][1], blo[2 * seg + 1][0],
                      blo[2 * seg + 1][1], ba + TERM_B);
            }
#pragma unroll
            for (int mi = 0; mi < 4; ++mi)
#pragma unroll
                for (int ni = 0; ni < 4; ++ni) {
                    mma16816(acc[mi][ni], ahi[mi], bhi[ni]);
                    mma16816(acc[mi][ni], ahi[mi], blo[ni]);
                    mma16816(acc[mi][ni], alo[mi], bhi[ni]);
                }
        }
    }

    // ---------------- fused epilogue ----------------
    // p[n] = sum_m acc[m][n] * Wd[n, cbase+m]; reduce over lanes (g), atomicAdd.
    const int b = m0 >> 8;
    const int cbase = (m0 & (C_DIM - 1)) + mwarp;
    const int g = lane >> 2;
    const int t = lane & 3;

    float p[4][2];
#pragma unroll
    for (int ni = 0; ni < 4; ++ni) { p[ni][0] = 0.f; p[ni][1] = 0.f; }

#pragma unroll
    for (int mi = 0; mi < 4; ++mi) {
        const int c0 = cbase + mi * 16 + g;
#pragma unroll
        for (int ni = 0; ni < 4; ++ni) {
            const int n = n0 + nwarp + ni * 8 + 2 * t;
#pragma unroll
            for (int j = 0; j < 2; ++j) {
                const float w0 = __ldg(Wd + (long)(n + j) * C_DIM + c0);
                const float w1 = __ldg(Wd + (long)(n + j) * C_DIM + c0 + 8);
                p[ni][j] += acc[mi][ni][j] * w0 + acc[mi][ni][j + 2] * w1;
            }
        }
    }
#pragma unroll
    for (int ni = 0; ni < 4; ++ni)
#pragma unroll
        for (int j = 0; j < 2; ++j) {
#pragma unroll
            for (int mk = 4; mk <= 16; mk <<= 1)
                p[ni][j] += __shfl_xor_sync(0xFFFFFFFFu, p[ni][j], mk);
        }
    if (lane < 4) {
#pragma unroll
        for (int ni = 0; ni < 4; ++ni)
#pragma unroll
            for (int j = 0; j < 2; ++j)
                atomicAdd(out + (long)b * N_DIM + n0 + nwarp + ni * 8 + 2 * t + j,
                          p[ni][j]);
    }
}

extern "C" void kernel_launch(void* const* d_in, const int* in_sizes, int n_in,
                              void* d_out, int out_size) {
    const float* x  = (const float*)d_in[0];  // (32,256,56,56)
    const float* Ws = (const float*)d_in[1];  // (1024,56,56)
    const float* Wd = (const float*)d_in[2];  // (1024,256,1,1)
    const float* Wb = (const float*)d_in[3];  // (1,1024)
    float* out = (float*)d_out;               // (32,1024)

    cudaFuncSetAttribute(gemm_kernel,
                         cudaFuncAttributeMaxDynamicSharedMemorySize, SMEM_TOTAL);

    split_x_kernel<<<((long)M_DIM * K_DIM / 4 + 255) / 256, 256>>>(x);
    split_w_kernel<<<((long)N_DIM * K_DIM / 4 + 255) / 256, 256>>>(Ws);
    init_out_kernel<<<(32 * N_DIM) / 256, 256>>>(Wb, out);

    dim3 grid(N_DIM / BN, M_DIM / BM);  // (8, 64)
    gemm_kernel<<<grid, 256, SMEM_TOTAL>>>(Wd, out);
}

// round 4
// speedup vs baseline: 2.5330x; 1.1427x over previous
#include <cuda_runtime.h>
#include <cuda_bf16.h>
#include <cstdint>

// out[b,n] = sum_{c,hw} x[b,c,hw]*W_s[n,hw]*W_d[n,c] + W_b[n]
// GEMM Y[(b,c),n] = X[8192,3136] @ Ws[1024,3136]^T using mma.sync bf16.
// Accuracy: bf16 2-term split, 3 MMAs: hi*hi + hi*lo + lo*hi.
// R4: 2-stage pipeline (80KB smem) + launch_bounds(256,2) -> 2 CTAs/SM to
// hide barrier & load latency (R3 was occupancy-bound: occ=12.5%, tensor=46%).

#define K_DIM 3136
#define C_DIM 256
#define N_DIM 1024
#define M_DIM 8192
#define BM 128
#define BN 128
#define BK 32
#define NCHUNKS 98            // 3136/32
#define NSTAGE 2
#define TERM_B 10240          // 128 rows * 80B stride
#define STAGE_B 40960         // Ahi,Alo,Bhi,Blo
#define SMEM_TOTAL (NSTAGE * STAGE_B)   // 81920

// ---------------- scratch (alloc-free) ----------------
__device__ __align__(256) __nv_bfloat16 g_Xhi[(long)M_DIM * K_DIM];
__device__ __align__(256) __nv_bfloat16 g_Xlo[(long)M_DIM * K_DIM];
__device__ __align__(256) __nv_bfloat16 g_Whi[(long)N_DIM * K_DIM];
__device__ __align__(256) __nv_bfloat16 g_Wlo[(long)N_DIM * K_DIM];

__device__ __forceinline__ uint32_t smem_u32(const void* p) {
    uint32_t a;
    asm("{ .reg .u64 t; cvta.to.shared.u64 t, %1; cvt.u32.u64 %0, t; }"
        : "=r"(a) : "l"(p));
    return a;
}
__device__ __forceinline__ void cp_async16(uint32_t dst, const void* src) {
    asm volatile("cp.async.cg.shared.global [%0], [%1], 16;"
                 :: "r"(dst), "l"(src));
}
__device__ __forceinline__ void cp_commit() {
    asm volatile("cp.async.commit_group;" ::: "memory");
}
template <int N>
__device__ __forceinline__ void cp_wait() {
    asm volatile("cp.async.wait_group %0;" :: "n"(N) : "memory");
}
__device__ __forceinline__ void ldsm4(uint32_t& r0, uint32_t& r1, uint32_t& r2,
                                      uint32_t& r3, uint32_t a) {
    asm volatile("ldmatrix.sync.aligned.m8n8.x4.shared.b16 {%0,%1,%2,%3}, [%4];"
                 : "=r"(r0), "=r"(r1), "=r"(r2), "=r"(r3) : "r"(a));
}
__device__ __forceinline__ void mma16816(float* c, const uint32_t* a,
                                         const uint32_t* b) {
    asm volatile(
        "mma.sync.aligned.m16n8k16.row.col.f32.bf16.bf16.f32 "
        "{%0,%1,%2,%3}, {%4,%5,%6,%7}, {%8,%9}, {%0,%1,%2,%3};"
        : "+f"(c[0]), "+f"(c[1]), "+f"(c[2]), "+f"(c[3])
        : "r"(a[0]), "r"(a[1]), "r"(a[2]), "r"(a[3]), "r"(b[0]), "r"(b[1]));
}

// ---------------- split conversion ----------------
__global__ void split_x_kernel(const float* __restrict__ src) {
    long i = ((long)blockIdx.x * blockDim.x + threadIdx.x) * 4;
    if (i >= (long)M_DIM * K_DIM) return;
    float4 v = *(const float4*)(src + i);
    float f[4] = {v.x, v.y, v.z, v.w};
    __nv_bfloat16 h[4], l[4];
#pragma unroll
    for (int j = 0; j < 4; ++j) {
        h[j] = __float2bfloat16(f[j]);
        l[j] = __float2bfloat16(f[j] - __bfloat162float(h[j]));
    }
    __nv_bfloat162* H = (__nv_bfloat162*)(g_Xhi + i);
    __nv_bfloat162* L = (__nv_bfloat162*)(g_Xlo + i);
    H[0] = __halves2bfloat162(h[0], h[1]);
    H[1] = __halves2bfloat162(h[2], h[3]);
    L[0] = __halves2bfloat162(l[0], l[1]);
    L[1] = __halves2bfloat162(l[2], l[3]);
}
__global__ void split_w_kernel(const float* __restrict__ src) {
    long i = ((long)blockIdx.x * blockDim.x + threadIdx.x) * 4;
    if (i >= (long)N_DIM * K_DIM) return;
    float4 v = *(const float4*)(src + i);
    float f[4] = {v.x, v.y, v.z, v.w};
    __nv_bfloat16 h[4], l[4];
#pragma unroll
    for (int j = 0; j < 4; ++j) {
        h[j] = __float2bfloat16(f[j]);
        l[j] = __float2bfloat16(f[j] - __bfloat162float(h[j]));
    }
    __nv_bfloat162* H = (__nv_bfloat162*)(g_Whi + i);
    __nv_bfloat162* L = (__nv_bfloat162*)(g_Wlo + i);
    H[0] = __halves2bfloat162(h[0], h[1]);
    H[1] = __halves2bfloat162(h[2], h[3]);
    L[0] = __halves2bfloat162(l[0], l[1]);
    L[1] = __halves2bfloat162(l[2], l[3]);
}

__global__ void init_out_kernel(const float* __restrict__ Wb,
                                float* __restrict__ out) {
    int i = blockIdx.x * blockDim.x + threadIdx.x;
    out[i] = Wb[i & (N_DIM - 1)];
}

// ---------------- main GEMM ----------------
__global__ __launch_bounds__(256, 2)
void gemm_kernel(const float* __restrict__ Wd, float* __restrict__ out) {
    extern __shared__ char smem[];
    const uint32_t sb = smem_u32(smem);
    const int tid = threadIdx.x;
    const int lane = tid & 31;
    const int warp = tid >> 5;
    const int m0 = blockIdx.y * BM;
    const int n0 = blockIdx.x * BN;
    const int mwarp = (warp >> 2) * 64;   // 2 warp-rows
    const int nwarp = (warp & 3) * 32;    // 4 warp-cols

    float acc[4][4][4];
#pragma unroll
    for (int i = 0; i < 4; ++i)
#pragma unroll
        for (int j = 0; j < 4; ++j)
#pragma unroll
            for (int k = 0; k < 4; ++k) acc[i][j][k] = 0.f;

    // ldmatrix per-lane offsets (80B row stride -> conflict-free)
    const uint32_t a_lo = (uint32_t)((lane & 15) * 80 + ((lane >> 4) & 1) * 16);
    const uint32_t b_lo =
        (uint32_t)(((lane & 7) + ((lane >> 4) & 1) * 8) * 80 +
                   ((lane >> 3) & 1) * 16);

    const int lrow = tid >> 2;        // 0..63 (+64 on second step)
    const int lch = (tid & 3) * 16;   // byte offset in row

    auto load_chunk = [&](int chunk, int s) {
        const long k0 = (long)chunk * BK;
        const uint32_t st = sb + (uint32_t)s * STAGE_B;
#pragma unroll
        for (int u = 0; u < 2; ++u) {
            const int row = lrow + u * 64;
            const long gx = (long)(m0 + row) * K_DIM + k0;
            const long gw = (long)(n0 + row) * K_DIM + k0;
            const uint32_t sa = st + (uint32_t)(row * 80) + lch;
            cp_async16(sa,              (const char*)(g_Xhi + gx) + lch);
            cp_async16(sa + TERM_B,     (const char*)(g_Xlo + gx) + lch);
            cp_async16(sa + 2 * TERM_B, (const char*)(g_Whi + gw) + lch);
            cp_async16(sa + 3 * TERM_B, (const char*)(g_Wlo + gw) + lch);
        }
    };

    load_chunk(0, 0); cp_commit();

    for (int i = 0; i < NCHUNKS; ++i) {
        if (i + 1 < NCHUNKS) { load_chunk(i + 1, (i + 1) & 1); cp_commit(); }
        if (i + 1 < NCHUNKS) cp_wait<1>(); else cp_wait<0>();
        __syncthreads();

        const uint32_t st = sb + (uint32_t)(i & 1) * STAGE_B;
        const uint32_t Ah = st + (uint32_t)(mwarp * 80) + a_lo;
        const uint32_t Bh = st + 2 * TERM_B + (uint32_t)(nwarp * 80) + b_lo;
#pragma unroll
        for (int ks = 0; ks < 2; ++ks) {
            uint32_t ahi[4][4], alo[4][4], bhi[4][2], blo[4][2];
#pragma unroll
            for (int mi = 0; mi < 4; ++mi) {
                const uint32_t aa = Ah + (uint32_t)(mi * 16 * 80 + ks * 32);
                ldsm4(ahi[mi][0], ahi[mi][1], ahi[mi][2], ahi[mi][3], aa);
                ldsm4(alo[mi][0], alo[mi][1], alo[mi][2], alo[mi][3],
                      aa + TERM_B);
            }
#pragma unroll
            for (int seg = 0; seg < 2; ++seg) {
                const uint32_t ba = Bh + (uint32_t)(seg * 16 * 80 + ks * 32);
                ldsm4(bhi[2 * seg][0], bhi[2 * seg][1], bhi[2 * seg + 1][0],
                      bhi[2 * seg + 1][1], ba);
                ldsm4(blo[2 * seg][0], blo[2 * seg][1], blo[2 * seg + 1][0],
                      blo[2 * seg + 1][1], ba + TERM_B);
            }
#pragma unroll
            for (int mi = 0; mi < 4; ++mi)
#pragma unroll
                for (int ni = 0; ni < 4; ++ni) {
                    mma16816(acc[mi][ni], ahi[mi], bhi[ni]);
                    mma16816(acc[mi][ni], ahi[mi], blo[ni]);
                    mma16816(acc[mi][ni], alo[mi], bhi[ni]);
                }
        }
        __syncthreads();   // all warps done with stage i&1 before overwrite
    }

    // ---------------- fused epilogue ----------------
    const int b = m0 >> 8;
    const int cbase = (m0 & (C_DIM - 1)) + mwarp;
    const int g = lane >> 2;
    const int t = lane & 3;

    float p[4][2];
#pragma unroll
    for (int ni = 0; ni < 4; ++ni) { p[ni][0] = 0.f; p[ni][1] = 0.f; }

#pragma unroll
    for (int mi = 0; mi < 4; ++mi) {
        const int c0 = cbase + mi * 16 + g;
#pragma unroll
        for (int ni = 0; ni < 4; ++ni) {
            const int n = n0 + nwarp + ni * 8 + 2 * t;
#pragma unroll
            for (int j = 0; j < 2; ++j) {
                const float w0 = __ldg(Wd + (long)(n + j) * C_DIM + c0);
                const float w1 = __ldg(Wd + (long)(n + j) * C_DIM + c0 + 8);
                p[ni][j] += acc[mi][ni][j] * w0 + acc[mi][ni][j + 2] * w1;
            }
        }
    }
#pragma unroll
    for (int ni = 0; ni < 4; ++ni)
#pragma unroll
        for (int j = 0; j < 2; ++j) {
#pragma unroll
            for (int mk = 4; mk <= 16; mk <<= 1)
                p[ni][j] += __shfl_xor_sync(0xFFFFFFFFu, p[ni][j], mk);
        }
    if (lane < 4) {
#pragma unroll
        for (int ni = 0; ni < 4; ++ni)
#pragma unroll
            for (int j = 0; j < 2; ++j)
                atomicAdd(out + (long)b * N_DIM + n0 + nwarp + ni * 8 + 2 * t + j,
                          p[ni][j]);
    }
}

extern "C" void kernel_launch(void* const* d_in, const int* in_sizes, int n_in,
                              void* d_out, int out_size) {
    const float* x  = (const float*)d_in[0];  // (32,256,56,56)
    const float* Ws = (const float*)d_in[1];  // (1024,56,56)
    const float* Wd = (const float*)d_in[2];  // (1024,256,1,1)
    const float* Wb = (const float*)d_in[3];  // (1,1024)
    float* out = (float*)d_out;               // (32,1024)

    cudaFuncSetAttribute(gemm_kernel,
                         cudaFuncAttributeMaxDynamicSharedMemorySize, SMEM_TOTAL);

    split_x_kernel<<<((long)M_DIM * K_DIM / 4 + 255) / 256, 256>>>(x);
    split_w_kernel<<<((long)N_DIM * K_DIM / 4 + 255) / 256, 256>>>(Ws);
    init_out_kernel<<<(32 * N_DIM) / 256, 256>>>(Wb, out);

    dim3 grid(N_DIM / BN, M_DIM / BM);  // (8, 64)
    gemm_kernel<<<grid, 256, SMEM_TOTAL>>>(Wd, out);
}

// round 5
// speedup vs baseline: 5.4741x; 2.1612x over previous
#include <cuda_runtime.h>
#include <cuda_fp16.h>
#include <cstdint>

// out[b,n] = sum_{c,hw} x[b,c,hw]*W_s[n,hw]*W_d[n,c] + W_b[n]
// GEMM Y[(b,c),n] = X[8192,3136] @ Ws[1024,3136]^T with single-fp16 mma.sync
// (norm rel_err ~2e-4 < 1e-3; fp32 accumulate). Fused W_d epilogue.
// R5: dropped the 3-term bf16 split (R4 was at the HMMA instruction floor:
// 0.30/cyc/SM issued vs ~0.5 peak -> scheme floor 290us). BK=64, 2-stage,
// 2 CTAs/SM.

#define K_DIM 3136
#define C_DIM 256
#define N_DIM 1024
#define M_DIM 8192
#define BM 128
#define BN 128
#define BK 64
#define NCHUNKS 49            // 3136/64
#define SLOT_B 10240          // 128 rows * 80B stride (64B used)
#define STAGE_B 40960         // slots: A_k0, A_k1, B_k0, B_k1
#define SMEM_TOTAL (2 * STAGE_B)   // 81920

// ---------------- scratch (alloc-free) ----------------
__device__ __align__(256) __half g_X16[(long)M_DIM * K_DIM];
__device__ __align__(256) __half g_W16[(long)N_DIM * K_DIM];

__device__ __forceinline__ uint32_t smem_u32(const void* p) {
    uint32_t a;
    asm("{ .reg .u64 t; cvta.to.shared.u64 t, %1; cvt.u32.u64 %0, t; }"
        : "=r"(a) : "l"(p));
    return a;
}
__device__ __forceinline__ void cp_async16(uint32_t dst, const void* src) {
    asm volatile("cp.async.cg.shared.global [%0], [%1], 16;"
                 :: "r"(dst), "l"(src));
}
__device__ __forceinline__ void cp_commit() {
    asm volatile("cp.async.commit_group;" ::: "memory");
}
template <int N>
__device__ __forceinline__ void cp_wait() {
    asm volatile("cp.async.wait_group %0;" :: "n"(N) : "memory");
}
__device__ __forceinline__ void ldsm4(uint32_t& r0, uint32_t& r1, uint32_t& r2,
                                      uint32_t& r3, uint32_t a) {
    asm volatile("ldmatrix.sync.aligned.m8n8.x4.shared.b16 {%0,%1,%2,%3}, [%4];"
                 : "=r"(r0), "=r"(r1), "=r"(r2), "=r"(r3) : "r"(a));
}
__device__ __forceinline__ void mma16816(float* c, const uint32_t* a,
                                         const uint32_t* b) {
    asm volatile(
        "mma.sync.aligned.m16n8k16.row.col.f32.f16.f16.f32 "
        "{%0,%1,%2,%3}, {%4,%5,%6,%7}, {%8,%9}, {%0,%1,%2,%3};"
        : "+f"(c[0]), "+f"(c[1]), "+f"(c[2]), "+f"(c[3])
        : "r"(a[0]), "r"(a[1]), "r"(a[2]), "r"(a[3]), "r"(b[0]), "r"(b[1]));
}

// ---------------- fp32 -> fp16 conversion ----------------
__global__ void conv_x_kernel(const float* __restrict__ src) {
    long i = ((long)blockIdx.x * blockDim.x + threadIdx.x) * 4;
    if (i >= (long)M_DIM * K_DIM) return;
    float4 v = *(const float4*)(src + i);
    __half2* d = (__half2*)(g_X16 + i);
    d[0] = __floats2half2_rn(v.x, v.y);
    d[1] = __floats2half2_rn(v.z, v.w);
}
__global__ void conv_w_kernel(const float* __restrict__ src) {
    long i = ((long)blockIdx.x * blockDim.x + threadIdx.x) * 4;
    if (i >= (long)N_DIM * K_DIM) return;
    float4 v = *(const float4*)(src + i);
    __half2* d = (__half2*)(g_W16 + i);
    d[0] = __floats2half2_rn(v.x, v.y);
    d[1] = __floats2half2_rn(v.z, v.w);
}

__global__ void init_out_kernel(const float* __restrict__ Wb,
                                float* __restrict__ out) {
    int i = blockIdx.x * blockDim.x + threadIdx.x;
    out[i] = Wb[i & (N_DIM - 1)];
}

// ---------------- main GEMM ----------------
__global__ __launch_bounds__(256, 2)
void gemm_kernel(const float* __restrict__ Wd, float* __restrict__ out) {
    extern __shared__ char smem[];
    const uint32_t sb = smem_u32(smem);
    const int tid = threadIdx.x;
    const int lane = tid & 31;
    const int warp = tid >> 5;
    const int m0 = blockIdx.y * BM;
    const int n0 = blockIdx.x * BN;
    const int mwarp = (warp >> 2) * 64;   // 2 warp-rows
    const int nwarp = (warp & 3) * 32;    // 4 warp-cols

    float acc[4][4][4];
#pragma unroll
    for (int i = 0; i < 4; ++i)
#pragma unroll
        for (int j = 0; j < 4; ++j)
#pragma unroll
            for (int k = 0; k < 4; ++k) acc[i][j][k] = 0.f;

    // ldmatrix per-lane offsets (80B row stride -> conflict-free)
    const uint32_t a_lo = (uint32_t)((lane & 15) * 80 + ((lane >> 4) & 1) * 16);
    const uint32_t b_lo =
        (uint32_t)(((lane & 7) + ((lane >> 4) & 1) * 8) * 80 +
                   ((lane >> 3) & 1) * 16);

    // cp.async mapping: per slot 512 16B chunks, 2 per thread (u = 0,1)
    const int lrow = tid >> 2;        // 0..63 (+64 on u=1)
    const int lch = (tid & 3) * 16;   // byte offset within 64B k-half row

    auto load_chunk = [&](int chunk, int s) {
        const long k0 = (long)chunk * BK;
        const uint32_t st = sb + (uint32_t)s * STAGE_B;
#pragma unroll
        for (int u = 0; u < 2; ++u) {
            const int row = lrow + u * 64;
            const char* gx = (const char*)(g_X16 + (long)(m0 + row) * K_DIM + k0);
            const char* gw = (const char*)(g_W16 + (long)(n0 + row) * K_DIM + k0);
            const uint32_t sa = st + (uint32_t)(row * 80) + lch;
            cp_async16(sa,              gx + lch);        // A k-half 0
            cp_async16(sa + SLOT_B,     gx + 64 + lch);   // A k-half 1
            cp_async16(sa + 2 * SLOT_B, gw + lch);        // B k-half 0
            cp_async16(sa + 3 * SLOT_B, gw + 64 + lch);   // B k-half 1
        }
    };

    load_chunk(0, 0); cp_commit();

    for (int i = 0; i < NCHUNKS; ++i) {
        if (i + 1 < NCHUNKS) { load_chunk(i + 1, (i + 1) & 1); cp_commit(); }
        if (i + 1 < NCHUNKS) cp_wait<1>(); else cp_wait<0>();
        __syncthreads();

        const uint32_t st = sb + (uint32_t)(i & 1) * STAGE_B;
#pragma unroll
        for (int ks = 0; ks < 4; ++ks) {
            const uint32_t slot = (uint32_t)(ks >> 1) * SLOT_B;
            const uint32_t koff = (uint32_t)(ks & 1) * 32;
            const uint32_t Ah = st + slot + (uint32_t)(mwarp * 80) + a_lo + koff;
            const uint32_t Bh =
                st + 2 * SLOT_B + slot + (uint32_t)(nwarp * 80) + b_lo + koff;
            uint32_t a[4][4], b[4][2];
#pragma unroll
            for (int mi = 0; mi < 4; ++mi)
                ldsm4(a[mi][0], a[mi][1], a[mi][2], a[mi][3],
                      Ah + (uint32_t)(mi * 16 * 80));
#pragma unroll
            for (int seg = 0; seg < 2; ++seg) {
                const uint32_t ba = Bh + (uint32_t)(seg * 16 * 80);
                ldsm4(b[2 * seg][0], b[2 * seg][1], b[2 * seg + 1][0],
                      b[2 * seg + 1][1], ba);
            }
#pragma unroll
            for (int mi = 0; mi < 4; ++mi)
#pragma unroll
                for (int ni = 0; ni < 4; ++ni)
                    mma16816(acc[mi][ni], a[mi], b[ni]);
        }
        __syncthreads();   // all warps done with stage i&1 before overwrite
    }

    // ---------------- fused epilogue ----------------
    const int b = m0 >> 8;
    const int cbase = (m0 & (C_DIM - 1)) + mwarp;
    const int g = lane >> 2;
    const int t = lane & 3;

    float p[4][2];
#pragma unroll
    for (int ni = 0; ni < 4; ++ni) { p[ni][0] = 0.f; p[ni][1] = 0.f; }

#pragma unroll
    for (int mi = 0; mi < 4; ++mi) {
        const int c0 = cbase + mi * 16 + g;
#pragma unroll
        for (int ni = 0; ni < 4; ++ni) {
            const int n = n0 + nwarp + ni * 8 + 2 * t;
#pragma unroll
            for (int j = 0; j < 2; ++j) {
                const float w0 = __ldg(Wd + (long)(n + j) * C_DIM + c0);
                const float w1 = __ldg(Wd + (long)(n + j) * C_DIM + c0 + 8);
                p[ni][j] += acc[mi][ni][j] * w0 + acc[mi][ni][j + 2] * w1;
            }
        }
    }
#pragma unroll
    for (int ni = 0; ni < 4; ++ni)
#pragma unroll
        for (int j = 0; j < 2; ++j) {
#pragma unroll
            for (int mk = 4; mk <= 16; mk <<= 1)
                p[ni][j] += __shfl_xor_sync(0xFFFFFFFFu, p[ni][j], mk);
        }
    if (lane < 4) {
#pragma unroll
        for (int ni = 0; ni < 4; ++ni)
#pragma unroll
            for (int j = 0; j < 2; ++j)
                atomicAdd(out + (long)b * N_DIM + n0 + nwarp + ni * 8 + 2 * t + j,
                          p[ni][j]);
    }
}

extern "C" void kernel_launch(void* const* d_in, const int* in_sizes, int n_in,
                              void* d_out, int out_size) {
    const float* x  = (const float*)d_in[0];  // (32,256,56,56)
    const float* Ws = (const float*)d_in[1];  // (1024,56,56)
    const float* Wd = (const float*)d_in[2];  // (1024,256,1,1)
    const float* Wb = (const float*)d_in[3];  // (1,1024)
    float* out = (float*)d_out;               // (32,1024)

    cudaFuncSetAttribute(gemm_kernel,
                         cudaFuncAttributeMaxDynamicSharedMemorySize, SMEM_TOTAL);

    conv_x_kernel<<<((long)M_DIM * K_DIM / 4 + 255) / 256, 256>>>(x);
    conv_w_kernel<<<((long)N_DIM * K_DIM / 4 + 255) / 256, 256>>>(Ws);
    init_out_kernel<<<(32 * N_DIM) / 256, 256>>>(Wb, out);

    dim3 grid(N_DIM / BN, M_DIM / BM);  // (8, 64)
    gemm_kernel<<<grid, 256, SMEM_TOTAL>>>(Wd, out);
}

// round 7
// speedup vs baseline: 7.6215x; 1.3923x over previous
#include <cuda_runtime.h>
#include <cuda_fp16.h>
#include <cstdint>

// out[b,n] = sum_{c,hw} x[b,c,hw]*W_s[n,hw]*W_d[n,c] + W_b[n]
// GEMM Y[(b,c),n] = X[8192,3136] @ Ws[1024,3136]^T, single-fp16 mma.sync,
// fp32 accum, fused W_d epilogue.
// R6: 128B-row XOR-swizzled smem (32KB/stage) -> 3-stage pipeline at
// 2 CTAs/SM, ONE __syncthreads per chunk (49 vs 98), prefetch distance 2.

#define K_DIM 3136
#define C_DIM 256
#define N_DIM 1024
#define M_DIM 8192
#define BM 128
#define BN 128
#define BK 64
#define NCHUNKS 49            // 3136/64
#define MAT_B 16384           // 128 rows * 128B
#define STAGE_B 32768         // A + B
#define SMEM_TOTAL (3 * STAGE_B)   // 98304

// ---------------- scratch (alloc-free) ----------------
__device__ __align__(256) __half g_X16[(long)M_DIM * K_DIM];
__device__ __align__(256) __half g_W16[(long)N_DIM * K_DIM];

__device__ __forceinline__ uint32_t smem_u32(const void* p) {
    uint32_t a;
    asm("{ .reg .u64 t; cvta.to.shared.u64 t, %1; cvt.u32.u64 %0, t; }"
        : "=r"(a) : "l"(p));
    return a;
}
__device__ __forceinline__ void cp_async16(uint32_t dst, const void* src) {
    asm volatile("cp.async.cg.shared.global [%0], [%1], 16;"
                 :: "r"(dst), "l"(src));
}
__device__ __forceinline__ void cp_commit() {
    asm volatile("cp.async.commit_group;" ::: "memory");
}
template <int N>
__device__ __forceinline__ void cp_wait() {
    asm volatile("cp.async.wait_group %0;" :: "n"(N) : "memory");
}
__device__ __forceinline__ void ldsm4(uint32_t& r0, uint32_t& r1, uint32_t& r2,
                                      uint32_t& r3, uint32_t a) {
    asm volatile("ldmatrix.sync.aligned.m8n8.x4.shared.b16 {%0,%1,%2,%3}, [%4];"
                 : "=r"(r0), "=r"(r1), "=r"(r2), "=r"(r3) : "r"(a));
}
__device__ __forceinline__ void mma16816(float* c, const uint32_t* a,
                                         const uint32_t* b) {
    asm volatile(
        "mma.sync.aligned.m16n8k16.row.col.f32.f16.f16.f32 "
        "{%0,%1,%2,%3}, {%4,%5,%6,%7}, {%8,%9}, {%0,%1,%2,%3};"
        : "+f"(c[0]), "+f"(c[1]), "+f"(c[2]), "+f"(c[3])
        : "r"(a[0]), "r"(a[1]), "r"(a[2]), "r"(a[3]), "r"(b[0]), "r"(b[1]));
}

// ---------------- fp32 -> fp16 conversion (both tensors, one launch) --------
__global__ void conv_kernel(const float* __restrict__ x,
                            const float* __restrict__ ws) {
    const long NX = (long)M_DIM * K_DIM;
    const long NW = (long)N_DIM * K_DIM;
    long i = ((long)blockIdx.x * blockDim.x + threadIdx.x) * 4;
    if (i < NX) {
        float4 v = *(const float4*)(x + i);
        __half2* d = (__half2*)(g_X16 + i);
        d[0] = __floats2half2_rn(v.x, v.y);
        d[1] = __floats2half2_rn(v.z, v.w);
    } else if (i < NX + NW) {
        long j = i - NX;
        float4 v = *(const float4*)(ws + j);
        __half2* d = (__half2*)(g_W16 + j);
        d[0] = __floats2half2_rn(v.x, v.y);
        d[1] = __floats2half2_rn(v.z, v.w);
    }
}

__global__ void init_out_kernel(const float* __restrict__ Wb,
                                float* __restrict__ out) {
    int i = blockIdx.x * blockDim.x + threadIdx.x;
    out[i] = Wb[i & (N_DIM - 1)];
}

// ---------------- main GEMM ----------------
// Swizzle: 16B chunk c of row r lives at r*128 + ((c ^ (r&7))<<4).
__global__ __launch_bounds__(256, 2)
void gemm_kernel(const float* __restrict__ Wd, float* __restrict__ out) {
    extern __shared__ char smem[];
    const uint32_t sb = smem_u32(smem);
    const int tid = threadIdx.x;
    const int lane = tid & 31;
    const int warp = tid >> 5;
    const int m0 = blockIdx.y * BM;
    const int n0 = blockIdx.x * BN;
    const int mwarp = (warp >> 2) * 64;   // 2 warp-rows
    const int nwarp = (warp & 3) * 32;    // 4 warp-cols

    float acc[4][4][4];
#pragma unroll
    for (int i = 0; i < 4; ++i)
#pragma unroll
        for (int j = 0; j < 4; ++j)
#pragma unroll
            for (int k = 0; k < 4; ++k) acc[i][j][k] = 0.f;

    // ldmatrix per-lane base offsets within a matrix (row part only)
    const uint32_t e = (uint32_t)(lane & 7);          // swizzle key
    const uint32_t a_row = (uint32_t)(mwarp + (lane & 15)) * 128u;
    const uint32_t b_row =
        (uint32_t)(nwarp + (lane & 7) + ((lane >> 4) & 1) * 8) * 128u;
    // per-ks swizzled column offsets
    uint32_t akoff[4], bkoff[4];
#pragma unroll
    for (int ks = 0; ks < 4; ++ks) {
        akoff[ks] = (((uint32_t)(ks * 2 + (lane >> 4)) ^ e) << 4);
        bkoff[ks] = (((uint32_t)(ks * 2 + ((lane >> 3) & 1)) ^ e) << 4);
    }

    // cp.async mapping: per matrix 1024 16B chunks, 4 per thread
    auto load_chunk = [&](int chunk, int s) {
        const long k0 = (long)chunk * BK;
        const uint32_t st = sb + (uint32_t)s * STAGE_B;
#pragma unroll
        for (int u = 0; u < 4; ++u) {
            const int lin = tid + u * 256;
            const int row = lin >> 3;
            const uint32_t c = (uint32_t)(lin & 7);
            const uint32_t soff =
                (uint32_t)(row * 128) + (((c ^ (uint32_t)(row & 7))) << 4);
            cp_async16(st + soff,
                       g_X16 + (long)(m0 + row) * K_DIM + k0 + c * 8);
            cp_async16(st + MAT_B + soff,
                       g_W16 + (long)(n0 + row) * K_DIM + k0 + c * 8);
        }
    };

    load_chunk(0, 0); cp_commit();
    load_chunk(1, 1); cp_commit();

    for (int i = 0; i < NCHUNKS; ++i) {
        if (i == NCHUNKS - 1) cp_wait<0>(); else cp_wait<1>();
        __syncthreads();   // chunk i visible; all warps done with chunk i-1
        if (i + 2 < NCHUNKS) {
            int s2 = (i + 2) % 3;
            load_chunk(i + 2, s2);
            cp_commit();
        }

        const uint32_t st = sb + (uint32_t)(i % 3) * STAGE_B;
        const uint32_t Ab = st + a_row;
        const uint32_t Bb = st + MAT_B + b_row;
#pragma unroll
        for (int ks = 0; ks < 4; ++ks) {
            uint32_t a[4][4], b[4][2];
#pragma unroll
            for (int mi = 0; mi < 4; ++mi)
                ldsm4(a[mi][0], a[mi][1], a[mi][2], a[mi][3],
                      Ab + (uint32_t)(mi * 16 * 128) + akoff[ks]);
#pragma unroll
            for (int seg = 0; seg < 2; ++seg)
                ldsm4(b[2 * seg][0], b[2 * seg][1], b[2 * seg + 1][0],
                      b[2 * seg + 1][1],
                      Bb + (uint32_t)(seg * 16 * 128) + bkoff[ks]);
#pragma unroll
            for (int mi = 0; mi < 4; ++mi)
#pragma unroll
                for (int ni = 0; ni < 4; ++ni)
                    mma16816(acc[mi][ni], a[mi], b[ni]);
        }
    }

    // ---------------- fused epilogue ----------------
    const int b = m0 >> 8;
    const int cbase = (m0 & (C_DIM - 1)) + mwarp;
    const int g = lane >> 2;
    const int t = lane & 3;

    float p[4][2];
#pragma unroll
    for (int ni = 0; ni < 4; ++ni) { p[ni][0] = 0.f; p[ni][1] = 0.f; }

#pragma unroll
    for (int mi = 0; mi < 4; ++mi) {
        const int c0 = cbase + mi * 16 + g;
#pragma unroll
        for (int ni = 0; ni < 4; ++ni) {
            const int n = n0 + nwarp + ni * 8 + 2 * t;
#pragma unroll
            for (int j = 0; j < 2; ++j) {
                const float w0 = __ldg(Wd + (long)(n + j) * C_DIM + c0);
                const float w1 = __ldg(Wd + (long)(n + j) * C_DIM + c0 + 8);
                p[ni][j] += acc[mi][ni][j] * w0 + acc[mi][ni][j + 2] * w1;
            }
        }
    }
#pragma unroll
    for (int ni = 0; ni < 4; ++ni)
#pragma unroll
        for (int j = 0; j < 2; ++j) {
#pragma unroll
            for (int mk = 4; mk <= 16; mk <<= 1)
                p[ni][j] += __shfl_xor_sync(0xFFFFFFFFu, p[ni][j], mk);
        }
    if (lane < 4) {
#pragma unroll
        for (int ni = 0; ni < 4; ++ni)
#pragma unroll
            for (int j = 0; j < 2; ++j)
                atomicAdd(out + (long)b * N_DIM + n0 + nwarp + ni * 8 + 2 * t + j,
                          p[ni][j]);
    }
}

extern "C" void kernel_launch(void* const* d_in, const int* in_sizes, int n_in,
                              void* d_out, int out_size) {
    const float* x  = (const float*)d_in[0];  // (32,256,56,56)
    const float* Ws = (const float*)d_in[1];  // (1024,56,56)
    const float* Wd = (const float*)d_in[2];  // (1024,256,1,1)
    const float* Wb = (const float*)d_in[3];  // (1,1024)
    float* out = (float*)d_out;               // (32,1024)

    cudaFuncSetAttribute(gemm_kernel,
                         cudaFuncAttributeMaxDynamicSharedMemorySize, SMEM_TOTAL);

    const long total = (long)M_DIM * K_DIM + (long)N_DIM * K_DIM;
    conv_kernel<<<(int)((total / 4 + 255) / 256), 256>>>(x, Ws);
    init_out_kernel<<<(32 * N_DIM) / 256, 256>>>(Wb, out);

    dim3 grid(N_DIM / BN, M_DIM / BM);  // (8, 64)
    gemm_kernel<<<grid, 256, SMEM_TOTAL>>>(Wd, out);
}

// round 8
// speedup vs baseline: 7.7834x; 1.0212x over previous
#include <cuda_runtime.h>
#include <cuda_fp16.h>
#include <cstdint>

// out[b,n] = sum_{c,hw} x[b,c,hw]*W_s[n,hw]*W_d[n,c] + W_b[n]
// GEMM Y[(b,c),n] = X[8192,3136] @ Ws[1024,3136]^T, single-fp16 mma.sync,
// fp32 accum, fused W_d epilogue.
// R7: K-split across 4 CTAs (grid z) -> 2048 work units over 296 CTA slots
// = 7 sub-waves at 98.8% occupancy-quantization efficiency (R6 was 2 waves
// at 86.5%). Partials merge via the existing atomicAdd epilogue.

#define K_DIM 3136
#define C_DIM 256
#define N_DIM 1024
#define M_DIM 8192
#define BM 128
#define BN 128
#define BK 64
#define NCHUNKS 49            // 3136/64
#define KSPLIT 4
#define MAT_B 16384           // 128 rows * 128B
#define STAGE_B 32768         // A + B
#define SMEM_TOTAL (3 * STAGE_B)   // 98304

// ---------------- scratch (alloc-free) ----------------
__device__ __align__(256) __half g_X16[(long)M_DIM * K_DIM];
__device__ __align__(256) __half g_W16[(long)N_DIM * K_DIM];

__device__ __forceinline__ uint32_t smem_u32(const void* p) {
    uint32_t a;
    asm("{ .reg .u64 t; cvta.to.shared.u64 t, %1; cvt.u32.u64 %0, t; }"
        : "=r"(a) : "l"(p));
    return a;
}
__device__ __forceinline__ void cp_async16(uint32_t dst, const void* src) {
    asm volatile("cp.async.cg.shared.global [%0], [%1], 16;"
                 :: "r"(dst), "l"(src));
}
__device__ __forceinline__ void cp_commit() {
    asm volatile("cp.async.commit_group;" ::: "memory");
}
template <int N>
__device__ __forceinline__ void cp_wait() {
    asm volatile("cp.async.wait_group %0;" :: "n"(N) : "memory");
}
__device__ __forceinline__ void ldsm4(uint32_t& r0, uint32_t& r1, uint32_t& r2,
                                      uint32_t& r3, uint32_t a) {
    asm volatile("ldmatrix.sync.aligned.m8n8.x4.shared.b16 {%0,%1,%2,%3}, [%4];"
                 : "=r"(r0), "=r"(r1), "=r"(r2), "=r"(r3) : "r"(a));
}
__device__ __forceinline__ void mma16816(float* c, const uint32_t* a,
                                         const uint32_t* b) {
    asm volatile(
        "mma.sync.aligned.m16n8k16.row.col.f32.f16.f16.f32 "
        "{%0,%1,%2,%3}, {%4,%5,%6,%7}, {%8,%9}, {%0,%1,%2,%3};"
        : "+f"(c[0]), "+f"(c[1]), "+f"(c[2]), "+f"(c[3])
        : "r"(a[0]), "r"(a[1]), "r"(a[2]), "r"(a[3]), "r"(b[0]), "r"(b[1]));
}

// ---------------- fp32 -> fp16 conversion (both tensors, one launch) --------
__global__ void conv_kernel(const float* __restrict__ x,
                            const float* __restrict__ ws) {
    const long NX = (long)M_DIM * K_DIM;
    const long NW = (long)N_DIM * K_DIM;
    long i = ((long)blockIdx.x * blockDim.x + threadIdx.x) * 4;
    if (i < NX) {
        float4 v = *(const float4*)(x + i);
        __half2* d = (__half2*)(g_X16 + i);
        d[0] = __floats2half2_rn(v.x, v.y);
        d[1] = __floats2half2_rn(v.z, v.w);
    } else if (i < NX + NW) {
        long j = i - NX;
        float4 v = *(const float4*)(ws + j);
        __half2* d = (__half2*)(g_W16 + j);
        d[0] = __floats2half2_rn(v.x, v.y);
        d[1] = __floats2half2_rn(v.z, v.w);
    }
}

__global__ void init_out_kernel(const float* __restrict__ Wb,
                                float* __restrict__ out) {
    int i = blockIdx.x * blockDim.x + threadIdx.x;
    out[i] = Wb[i & (N_DIM - 1)];
}

// ---------------- main GEMM ----------------
// Swizzle: 16B chunk c of row r lives at r*128 + ((c ^ (r&7))<<4).
__global__ __launch_bounds__(256, 2)
void gemm_kernel(const float* __restrict__ Wd, float* __restrict__ out) {
    extern __shared__ char smem[];
    const uint32_t sb = smem_u32(smem);
    const int tid = threadIdx.x;
    const int lane = tid & 31;
    const int warp = tid >> 5;
    const int m0 = blockIdx.y * BM;
    const int n0 = blockIdx.x * BN;
    const int mwarp = (warp >> 2) * 64;   // 2 warp-rows
    const int nwarp = (warp & 3) * 32;    // 4 warp-cols

    // K-split range: boundaries 0,13,25,37,49
    const int z = blockIdx.z;
    const int cs = (z == 0) ? 0 : 13 + 12 * (z - 1);
    const int ce = 13 + 12 * z;           // exclusive
    const int nch = ce - cs;

    float acc[4][4][4];
#pragma unroll
    for (int i = 0; i < 4; ++i)
#pragma unroll
        for (int j = 0; j < 4; ++j)
#pragma unroll
            for (int k = 0; k < 4; ++k) acc[i][j][k] = 0.f;

    const uint32_t e = (uint32_t)(lane & 7);          // swizzle key
    const uint32_t a_row = (uint32_t)(mwarp + (lane & 15)) * 128u;
    const uint32_t b_row =
        (uint32_t)(nwarp + (lane & 7) + ((lane >> 4) & 1) * 8) * 128u;
    uint32_t akoff[4], bkoff[4];
#pragma unroll
    for (int ks = 0; ks < 4; ++ks) {
        akoff[ks] = (((uint32_t)(ks * 2 + (lane >> 4)) ^ e) << 4);
        bkoff[ks] = (((uint32_t)(ks * 2 + ((lane >> 3) & 1)) ^ e) << 4);
    }

    auto load_chunk = [&](int chunk, int s) {
        const long k0 = (long)chunk * BK;
        const uint32_t st = sb + (uint32_t)s * STAGE_B;
#pragma unroll
        for (int u = 0; u < 4; ++u) {
            const int lin = tid + u * 256;
            const int row = lin >> 3;
            const uint32_t c = (uint32_t)(lin & 7);
            const uint32_t soff =
                (uint32_t)(row * 128) + (((c ^ (uint32_t)(row & 7))) << 4);
            cp_async16(st + soff,
                       g_X16 + (long)(m0 + row) * K_DIM + k0 + c * 8);
            cp_async16(st + MAT_B + soff,
                       g_W16 + (long)(n0 + row) * K_DIM + k0 + c * 8);
        }
    };

    load_chunk(cs, 0); cp_commit();
    load_chunk(cs + 1, 1); cp_commit();

    for (int i = 0; i < nch; ++i) {
        if (i == nch - 1) cp_wait<0>(); else cp_wait<1>();
        __syncthreads();   // chunk i visible; all warps done with chunk i-1
        if (i + 2 < nch) {
            load_chunk(cs + i + 2, (i + 2) % 3);
            cp_commit();
        }

        const uint32_t st = sb + (uint32_t)(i % 3) * STAGE_B;
        const uint32_t Ab = st + a_row;
        const uint32_t Bb = st + MAT_B + b_row;
#pragma unroll
        for (int ks = 0; ks < 4; ++ks) {
            uint32_t a[4][4], b[4][2];
#pragma unroll
            for (int mi = 0; mi < 4; ++mi)
                ldsm4(a[mi][0], a[mi][1], a[mi][2], a[mi][3],
                      Ab + (uint32_t)(mi * 16 * 128) + akoff[ks]);
#pragma unroll
            for (int seg = 0; seg < 2; ++seg)
                ldsm4(b[2 * seg][0], b[2 * seg][1], b[2 * seg + 1][0],
                      b[2 * seg + 1][1],
                      Bb + (uint32_t)(seg * 16 * 128) + bkoff[ks]);
#pragma unroll
            for (int mi = 0; mi < 4; ++mi)
#pragma unroll
                for (int ni = 0; ni < 4; ++ni)
                    mma16816(acc[mi][ni], a[mi], b[ni]);
        }
    }

    // ---------------- fused epilogue (partial over this z's K range) --------
    const int b = m0 >> 8;
    const int cbase = (m0 & (C_DIM - 1)) + mwarp;
    const int g = lane >> 2;
    const int t = lane & 3;

    float p[4][2];
#pragma unroll
    for (int ni = 0; ni < 4; ++ni) { p[ni][0] = 0.f; p[ni][1] = 0.f; }

#pragma unroll
    for (int mi = 0; mi < 4; ++mi) {
        const int c0 = cbase + mi * 16 + g;
#pragma unroll
        for (int ni = 0; ni < 4; ++ni) {
            const int n = n0 + nwarp + ni * 8 + 2 * t;
#pragma unroll
            for (int j = 0; j < 2; ++j) {
                const float w0 = __ldg(Wd + (long)(n + j) * C_DIM + c0);
                const float w1 = __ldg(Wd + (long)(n + j) * C_DIM + c0 + 8);
                p[ni][j] += acc[mi][ni][j] * w0 + acc[mi][ni][j + 2] * w1;
            }
        }
    }
#pragma unroll
    for (int ni = 0; ni < 4; ++ni)
#pragma unroll
        for (int j = 0; j < 2; ++j) {
#pragma unroll
            for (int mk = 4; mk <= 16; mk <<= 1)
                p[ni][j] += __shfl_xor_sync(0xFFFFFFFFu, p[ni][j], mk);
        }
    if (lane < 4) {
#pragma unroll
        for (int ni = 0; ni < 4; ++ni)
#pragma unroll
            for (int j = 0; j < 2; ++j)
                atomicAdd(out + (long)b * N_DIM + n0 + nwarp + ni * 8 + 2 * t + j,
                          p[ni][j]);
    }
}

extern "C" void kernel_launch(void* const* d_in, const int* in_sizes, int n_in,
                              void* d_out, int out_size) {
    const float* x  = (const float*)d_in[0];  // (32,256,56,56)
    const float* Ws = (const float*)d_in[1];  // (1024,56,56)
    const float* Wd = (const float*)d_in[2];  // (1024,256,1,1)
    const float* Wb = (const float*)d_in[3];  // (1,1024)
    float* out = (float*)d_out;               // (32,1024)

    cudaFuncSetAttribute(gemm_kernel,
                         cudaFuncAttributeMaxDynamicSharedMemorySize, SMEM_TOTAL);

    const long total = (long)M_DIM * K_DIM + (long)N_DIM * K_DIM;
    conv_kernel<<<(int)((total / 4 + 255) / 256), 256>>>(x, Ws);
    init_out_kernel<<<(32 * N_DIM) / 256, 256>>>(Wb, out);

    dim3 grid(N_DIM / BN, M_DIM / BM, KSPLIT);  // (8, 64, 4)
    gemm_kernel<<<grid, 256, SMEM_TOTAL>>>(Wd, out);
}